// round 2
// baseline (speedup 1.0000x reference)
#include <cuda_runtime.h>
#include <math.h>

#define T_TOTAL   65536
#define D_IN      128
#define H_DIM     128
#define NUM_HEADS 8
#define G3        384          // 3*H
#define WS_PAD    132          // padded row stride (floats)
#define OUT_COLS  (NUM_HEADS * H_DIM)

// Scratch for precomputed input gates ig[h][t][384]
__device__ float g_ig[(size_t)NUM_HEADS * T_TOTAL * G3 + G3];

// Numerically-stable sigmoid matching jax.nn.sigmoid semantics.
__device__ __forceinline__ float sigmoid_(float x) {
    if (x >= 0.f) {
        float e = expf(-x);
        return 1.f / (1.f + e);
    } else {
        float e = expf(x);
        return e / (1.f + e);
    }
}

__device__ __forceinline__ float dot4(float4 a, float4 b) {
    return a.x * b.x + a.y * b.y + a.z * b.z + a.w * b.w;
}

// ============================================================================
// Kernel 1: ig[h][t][g] = sum_d x[t,d] * Wih[h,g,d] + b[h,g]
// Tile 128(t) x 128(g) x K=128, 256 threads, 8x8 micro-tile, plain fp32.
// ============================================================================
#define GEMM_SMEM (2 * 128 * WS_PAD * 4)

__global__ void __launch_bounds__(256, 1)
gemm_ig_kernel(const float* __restrict__ x,
               const float* __restrict__ Wih,
               const float* __restrict__ bias) {
    extern __shared__ float sm[];
    float* sA = sm;                  // [128][132]
    float* sB = sm + 128 * WS_PAD;   // [128][132]

    const int tid = threadIdx.x;
    const int h   = blockIdx.z;
    const int g0  = blockIdx.y * 128;
    const int t0  = blockIdx.x * 128;

    // Load 128x128 tiles (float4, no swizzle).
    #pragma unroll
    for (int i = 0; i < 16; i++) {
        int idx = i * 256 + tid;
        int m   = idx >> 5;       // row 0..127
        int d4  = idx & 31;       // float4 col 0..31
        ((float4*)(sA + m * WS_PAD))[d4] =
            ((const float4*)(x + (size_t)(t0 + m) * D_IN))[d4];
        ((float4*)(sB + m * WS_PAD))[d4] =
            ((const float4*)(Wih + ((size_t)h * G3 + g0 + m) * D_IN))[d4];
    }
    __syncthreads();

    const int lane  = tid & 31, warp = tid >> 5;
    const int mi    = lane & 7, gi   = lane >> 3;
    const int warpM = warp >> 2, warpG = warp & 3;
    const int mBase = warpM * 64 + mi * 8;
    const int gBase = warpG * 32 + gi * 8;

    float acc[8][8];
    #pragma unroll
    for (int r = 0; r < 8; r++)
        #pragma unroll
        for (int c = 0; c < 8; c++) acc[r][c] = 0.f;

    #pragma unroll
    for (int k4 = 0; k4 < 32; k4++) {
        float4 av[8], bv[8];
        #pragma unroll
        for (int r = 0; r < 8; r++)
            av[r] = ((const float4*)(sA + (mBase + r) * WS_PAD))[k4];
        #pragma unroll
        for (int c = 0; c < 8; c++)
            bv[c] = ((const float4*)(sB + (gBase + c) * WS_PAD))[k4];
        #pragma unroll
        for (int r = 0; r < 8; r++)
            #pragma unroll
            for (int c = 0; c < 8; c++)
                acc[r][c] += dot4(av[r], bv[c]);
    }

    float bb[8];
    #pragma unroll
    for (int c = 0; c < 8; c++)
        bb[c] = bias[(size_t)h * G3 + g0 + gBase + c];

    #pragma unroll
    for (int r = 0; r < 8; r++) {
        size_t row  = (size_t)t0 + mBase + r;
        float* orow = g_ig + ((size_t)h * T_TOTAL + row) * G3 + g0 + gBase;
        #pragma unroll
        for (int c = 0; c < 8; c++)
            orow[c] = acc[r][c] + bb[c];
    }
}

// ============================================================================
// Kernel 2: one CTA per chain. Block b -> head = floor(log2(b+1)) so the
// longest chain (head 0) is scheduled in wave 1. 128 threads; thread j owns
// Whh rows j, 128+j, 256+j; h ping-ponged in SMEM, one barrier per step.
// Plain fp32 float4 math only.
// ============================================================================
#define RNN_SMEM ((G3 * WS_PAD + 256) * 4)

__global__ void __launch_bounds__(128, 1)
rnn_kernel(const float* __restrict__ Whh,
           const float* __restrict__ bn,
           float* __restrict__ out) {
    extern __shared__ float sm[];
    float* ws = sm;                      // [384][132] weights
    float* h0 = sm + G3 * WS_PAD;        // 128
    float* h1 = h0 + 128;                // 128

    const int j     = threadIdx.x;
    const int b     = blockIdx.x;
    const int head  = 31 - __clz(b + 1);
    const int chunk = b + 1 - (1 << head);
    const int Tc    = T_TOTAL >> head;

    // Load this head's Whh into padded SMEM (coalesced).
    const float* wsrc = Whh + (size_t)head * G3 * H_DIM;
    #pragma unroll 8
    for (int row = 0; row < G3; row++)
        ws[row * WS_PAD + j] = wsrc[(size_t)row * H_DIM + j];

    h0[j] = 0.f;
    const float bnj = bn[head * H_DIM + j];
    __syncthreads();

    const float4* Wr4 = (const float4*)(ws + (size_t)j * WS_PAD);
    const float4* Wz4 = (const float4*)(ws + (size_t)(128 + j) * WS_PAD);
    const float4* Wn4 = (const float4*)(ws + (size_t)(256 + j) * WS_PAD);

    const float* igp  = g_ig + ((size_t)head * T_TOTAL + (size_t)chunk * Tc) * G3;
    float*       outp = out + (size_t)chunk * Tc * OUT_COLS + head * H_DIM + j;

    float  hown = 0.f;
    float* hb   = h0;
    float* hw   = h1;

    #pragma unroll 1
    for (int t = 0; t < Tc; t++) {
        // Input gates for this step (latency hidden behind the dot products).
        const float* ig_t = igp + (size_t)t * G3;
        float igr = ig_t[j];
        float igz = ig_t[128 + j];
        float ign = ig_t[256 + j];

        // Stage h into registers (32 x float4, broadcast reads).
        float4 hreg[32];
        const float4* hb4 = (const float4*)hb;
        #pragma unroll
        for (int q = 0; q < 32; q++) hreg[q] = hb4[q];

        // r-gate dot
        float r0 = 0.f, r1 = 0.f, r2 = 0.f, r3 = 0.f;
        #pragma unroll
        for (int k = 0; k < 32; k += 4) {
            r0 += dot4(Wr4[k],     hreg[k]);
            r1 += dot4(Wr4[k + 1], hreg[k + 1]);
            r2 += dot4(Wr4[k + 2], hreg[k + 2]);
            r3 += dot4(Wr4[k + 3], hreg[k + 3]);
        }
        float r = sigmoid_(igr + ((r0 + r1) + (r2 + r3)));

        // z-gate dot
        float z0 = 0.f, z1 = 0.f, z2 = 0.f, z3 = 0.f;
        #pragma unroll
        for (int k = 0; k < 32; k += 4) {
            z0 += dot4(Wz4[k],     hreg[k]);
            z1 += dot4(Wz4[k + 1], hreg[k + 1]);
            z2 += dot4(Wz4[k + 2], hreg[k + 2]);
            z3 += dot4(Wz4[k + 3], hreg[k + 3]);
        }
        float z = sigmoid_(igz + ((z0 + z1) + (z2 + z3)));

        // n-gate dot
        float n0 = 0.f, n1 = 0.f, n2 = 0.f, n3 = 0.f;
        #pragma unroll
        for (int k = 0; k < 32; k += 4) {
            n0 += dot4(Wn4[k],     hreg[k]);
            n1 += dot4(Wn4[k + 1], hreg[k + 1]);
            n2 += dot4(Wn4[k + 2], hreg[k + 2]);
            n3 += dot4(Wn4[k + 3], hreg[k + 3]);
        }
        float an = (n0 + n1) + (n2 + n3);

        float n    = tanhf(ign + r * (an + bnj));
        float hnew = n + z * (hown - n);

        outp[(size_t)t * OUT_COLS] = hnew;
        hw[j] = hnew;
        hown  = hnew;
        __syncthreads();

        float* tmp = hw; hw = hb; hb = tmp;
    }
}

// ============================================================================
// Launch: GEMM (ig precompute) then recurrence; same stream => ordered.
// ============================================================================
extern "C" void kernel_launch(void* const* d_in, const int* in_sizes, int n_in,
                              void* d_out, int out_size) {
    const float* x   = (const float*)d_in[0];
    const float* Wih = (const float*)d_in[1];
    const float* Whh = (const float*)d_in[2];
    const float* bb  = (const float*)d_in[3];
    const float* bn  = (const float*)d_in[4];
    float* out = (float*)d_out;

    cudaFuncSetAttribute(gemm_ig_kernel,
                         cudaFuncAttributeMaxDynamicSharedMemorySize, GEMM_SMEM);
    cudaFuncSetAttribute(rnn_kernel,
                         cudaFuncAttributeMaxDynamicSharedMemorySize, RNN_SMEM);

    gemm_ig_kernel<<<dim3(512, 3, 8), 256, GEMM_SMEM>>>(x, Wih, bb);
    rnn_kernel<<<255, 128, RNN_SMEM>>>(Whh, bn, out);
}

// round 3
// speedup vs baseline: 1.9458x; 1.9458x over previous
#include <cuda_runtime.h>
#include <math.h>

#define T_TOTAL   65536
#define D_IN      128
#define H_DIM     128
#define NUM_HEADS 8
#define G3        384          // 3*H
#define WS_PAD    132          // padded row stride (floats) for GEMM tiles
#define OUT_COLS  (NUM_HEADS * H_DIM)
#define HPAD      144          // h buffer: 128 floats + 4-float pad per 32

// Scratch for precomputed input gates ig[h][t][384] (+ slack for prefetch)
__device__ float g_ig[(size_t)NUM_HEADS * T_TOTAL * G3 + G3];

__device__ __forceinline__ void ffma2(unsigned long long& acc,
                                      unsigned long long a,
                                      unsigned long long b) {
    asm("fma.rn.f32x2 %0, %1, %2, %0;" : "+l"(acc) : "l"(a), "l"(b));
}

__device__ __forceinline__ unsigned long long pack2(float lo, float hi) {
    unsigned long long r;
    asm("mov.b64 %0, {%1, %2};" : "=l"(r) : "f"(lo), "f"(hi));
    return r;
}

__device__ __forceinline__ float hsum2(unsigned long long v) {
    float lo, hi;
    asm("mov.b64 {%0, %1}, %2;" : "=f"(lo), "=f"(hi) : "l"(v));
    return lo + hi;
}

__device__ __forceinline__ float fast_sigmoid(float x) {
    x = fminf(fmaxf(x, -30.f), 30.f);
    float e = __expf(-x);
    return __fdividef(1.f, 1.f + e);
}

__device__ __forceinline__ float fast_tanh(float x) {
    x = fminf(fmaxf(x, -15.f), 15.f);
    float e = __expf(-2.f * x);
    return __fdividef(1.f - e, 1.f + e);
}

__device__ __forceinline__ float dot4(float4 a, float4 b) {
    return a.x * b.x + a.y * b.y + a.z * b.z + a.w * b.w;
}

// ============================================================================
// Kernel 1: ig[h][t][g] = sum_d x[t,d] * Wih[h,g,d] + b[h,g]
// (unchanged from round 2 — verified correct)
// ============================================================================
#define GEMM_SMEM (2 * 128 * WS_PAD * 4)

__global__ void __launch_bounds__(256, 1)
gemm_ig_kernel(const float* __restrict__ x,
               const float* __restrict__ Wih,
               const float* __restrict__ bias) {
    extern __shared__ float sm[];
    float* sA = sm;                  // [128][132]
    float* sB = sm + 128 * WS_PAD;   // [128][132]

    const int tid = threadIdx.x;
    const int h   = blockIdx.z;
    const int g0  = blockIdx.y * 128;
    const int t0  = blockIdx.x * 128;

    #pragma unroll
    for (int i = 0; i < 16; i++) {
        int idx = i * 256 + tid;
        int m   = idx >> 5;
        int d4  = idx & 31;
        ((float4*)(sA + m * WS_PAD))[d4] =
            ((const float4*)(x + (size_t)(t0 + m) * D_IN))[d4];
        ((float4*)(sB + m * WS_PAD))[d4] =
            ((const float4*)(Wih + ((size_t)h * G3 + g0 + m) * D_IN))[d4];
    }
    __syncthreads();

    const int lane  = tid & 31, warp = tid >> 5;
    const int mi    = lane & 7, gi   = lane >> 3;
    const int warpM = warp >> 2, warpG = warp & 3;
    const int mBase = warpM * 64 + mi * 8;
    const int gBase = warpG * 32 + gi * 8;

    float acc[8][8];
    #pragma unroll
    for (int r = 0; r < 8; r++)
        #pragma unroll
        for (int c = 0; c < 8; c++) acc[r][c] = 0.f;

    #pragma unroll
    for (int k4 = 0; k4 < 32; k4++) {
        float4 av[8], bv[8];
        #pragma unroll
        for (int r = 0; r < 8; r++)
            av[r] = ((const float4*)(sA + (mBase + r) * WS_PAD))[k4];
        #pragma unroll
        for (int c = 0; c < 8; c++)
            bv[c] = ((const float4*)(sB + (gBase + c) * WS_PAD))[k4];
        #pragma unroll
        for (int r = 0; r < 8; r++)
            #pragma unroll
            for (int c = 0; c < 8; c++)
                acc[r][c] += dot4(av[r], bv[c]);
    }

    float bb[8];
    #pragma unroll
    for (int c = 0; c < 8; c++)
        bb[c] = bias[(size_t)h * G3 + g0 + gBase + c];

    #pragma unroll
    for (int r = 0; r < 8; r++) {
        size_t row  = (size_t)t0 + mBase + r;
        float* orow = g_ig + ((size_t)h * T_TOTAL + row) * G3 + g0 + gBase;
        #pragma unroll
        for (int c = 0; c < 8; c++)
            orow[c] = acc[r][c] + bb[c];
    }
}

// ============================================================================
// Kernel 2: one CTA (512 threads) per chain; weights register-resident.
// Thread t: neuron j = t>>2, k-quarter ks = t&3. Holds 3x32 weights in regs
// (f32x2 pairs). Quarter-dots reduced over the 4-lane group via shfl_xor.
// Lane ks==0 writes h' to ping-ponged padded SMEM buffer; 1 barrier/step.
// Block b -> head floor(log2(b+1)) so head 0 (longest) runs in wave 1.
// ============================================================================
__global__ void __launch_bounds__(512, 1)
rnn_kernel(const float* __restrict__ Whh,
           const float* __restrict__ bn,
           float* __restrict__ out) {
    __shared__ __align__(16) float hbuf[2][HPAD];

    const int tid   = threadIdx.x;
    const int j     = tid >> 2;
    const int ks    = tid & 3;
    const int b     = blockIdx.x;
    const int head  = 31 - __clz(b + 1);
    const int chunk = b + 1 - (1 << head);
    const int Tc    = T_TOTAL >> head;

    // Load this thread's 96 weights into registers as f32x2 pairs.
    unsigned long long w[3][16];
    const float* wbase = Whh + (size_t)head * G3 * H_DIM;
    #pragma unroll
    for (int g = 0; g < 3; g++) {
        const float4* src =
            (const float4*)(wbase + (size_t)(g * 128 + j) * H_DIM + ks * 32);
        #pragma unroll
        for (int q = 0; q < 8; q++) {
            float4 v = src[q];
            w[g][2 * q]     = pack2(v.x, v.y);
            w[g][2 * q + 1] = pack2(v.z, v.w);
        }
    }

    if (tid < HPAD) hbuf[0][tid] = 0.f;
    const float bnj = bn[head * H_DIM + j];

    const float* igp  = g_ig + ((size_t)head * T_TOTAL + (size_t)chunk * Tc) * G3;
    float*       outp = out + (size_t)chunk * Tc * OUT_COLS + head * H_DIM + j;

    float igr = __ldcs(igp + j);
    float igz = __ldcs(igp + 128 + j);
    float ign = __ldcs(igp + 256 + j);
    float hprev = 0.f;
    int buf = 0;

    const int hoff = 36 * ks;   // padded float index of this thread's h slice
    __syncthreads();

    #pragma unroll 1
    for (int t = 0; t < Tc; t++) {
        // Prefetch next step's input gates (array slack covers the last step).
        const float* ignext = igp + G3;
        float pr = __ldcs(ignext + j);
        float pz = __ldcs(ignext + 128 + j);
        float pn = __ldcs(ignext + 256 + j);

        // Quarter dot products (h slice via conflict-free broadcast LDS.128).
        unsigned long long ar = 0, az = 0, an = 0;
        const ulonglong2* hsl = (const ulonglong2*)(hbuf[buf] + hoff);
        #pragma unroll
        for (int c4 = 0; c4 < 8; c4++) {
            ulonglong2 hv = hsl[c4];
            ffma2(ar, w[0][2 * c4],     hv.x);
            ffma2(ar, w[0][2 * c4 + 1], hv.y);
            ffma2(az, w[1][2 * c4],     hv.x);
            ffma2(az, w[1][2 * c4 + 1], hv.y);
            ffma2(an, w[2][2 * c4],     hv.x);
            ffma2(an, w[2][2 * c4 + 1], hv.y);
        }
        float dr = hsum2(ar), dz = hsum2(az), dn = hsum2(an);

        // Reduce across the 4-lane group (lanes 4j..4j+3).
        dr += __shfl_xor_sync(0xffffffffu, dr, 1);
        dz += __shfl_xor_sync(0xffffffffu, dz, 1);
        dn += __shfl_xor_sync(0xffffffffu, dn, 1);
        dr += __shfl_xor_sync(0xffffffffu, dr, 2);
        dz += __shfl_xor_sync(0xffffffffu, dz, 2);
        dn += __shfl_xor_sync(0xffffffffu, dn, 2);

        float r    = fast_sigmoid(igr + dr);
        float z    = fast_sigmoid(igz + dz);
        float n    = fast_tanh(ign + r * (dn + bnj));
        float hnew = n + z * (hprev - n);

        if (ks == 0) {
            hbuf[buf ^ 1][j + 4 * (j >> 5)] = hnew;
            __stcs(outp, hnew);
        }

        hprev = hnew;
        igr = pr; igz = pz; ign = pn;
        igp += G3;
        outp += OUT_COLS;
        __syncthreads();
        buf ^= 1;
    }
}

// ============================================================================
// Launch: GEMM (ig precompute) then recurrence; same stream => ordered.
// ============================================================================
extern "C" void kernel_launch(void* const* d_in, const int* in_sizes, int n_in,
                              void* d_out, int out_size) {
    const float* x   = (const float*)d_in[0];
    const float* Wih = (const float*)d_in[1];
    const float* Whh = (const float*)d_in[2];
    const float* bb  = (const float*)d_in[3];
    const float* bn  = (const float*)d_in[4];
    float* out = (float*)d_out;

    cudaFuncSetAttribute(gemm_ig_kernel,
                         cudaFuncAttributeMaxDynamicSharedMemorySize, GEMM_SMEM);

    gemm_ig_kernel<<<dim3(512, 3, 8), 256, GEMM_SMEM>>>(x, Wih, bb);
    rnn_kernel<<<255, 512>>>(Whh, bn, out);
}

// round 4
// speedup vs baseline: 1.9910x; 1.0232x over previous
#include <cuda_runtime.h>
#include <math.h>

#define T_TOTAL   65536
#define D_IN      128
#define H_DIM     128
#define NUM_HEADS 8
#define G3        384          // 3*H
#define WS_PAD    132          // padded row stride (floats) for GEMM tiles
#define OUT_COLS  (NUM_HEADS * H_DIM)
#define HBUF_LEN  136          // 64 + 4 pad + 64 + 4 pad

// Scratch for precomputed input gates ig[h][t][384] (+ slack for prefetch)
__device__ float g_ig[(size_t)NUM_HEADS * T_TOTAL * G3 + G3];

__device__ __forceinline__ void ffma2(unsigned long long& acc,
                                      unsigned long long a,
                                      unsigned long long b) {
    asm("fma.rn.f32x2 %0, %1, %2, %0;" : "+l"(acc) : "l"(a), "l"(b));
}

__device__ __forceinline__ unsigned long long pack2(float lo, float hi) {
    unsigned long long r;
    asm("mov.b64 %0, {%1, %2};" : "=l"(r) : "f"(lo), "f"(hi));
    return r;
}

__device__ __forceinline__ float hsum2(unsigned long long v) {
    float lo, hi;
    asm("mov.b64 {%0, %1}, %2;" : "=f"(lo), "=f"(hi) : "l"(v));
    return lo + hi;
}

__device__ __forceinline__ float fast_sigmoid(float x) {
    // No clamp needed: __expf(+-inf) and __fdividef(1, inf) behave correctly
    float e = __expf(-x);
    return __fdividef(1.f, 1.f + e);
}

__device__ __forceinline__ float fast_tanh(float x) {
    x = fminf(fmaxf(x, -15.f), 15.f);
    float e = __expf(-2.f * x);
    return __fdividef(1.f - e, 1.f + e);
}

// ============================================================================
// Kernel 1: ig[h][t][g] = sum_d x[t,d] * Wih[h,g,d] + b[h,g]
// Same structure as the validated round-3 GEMM, inner product upgraded to
// f32x2 FMAs (2x FMA pipe rate).
// ============================================================================
#define GEMM_SMEM (2 * 128 * WS_PAD * 4)

__global__ void __launch_bounds__(256, 1)
gemm_ig_kernel(const float* __restrict__ x,
               const float* __restrict__ Wih,
               const float* __restrict__ bias) {
    extern __shared__ float sm[];
    float* sA = sm;                  // [128][132]
    float* sB = sm + 128 * WS_PAD;   // [128][132]

    const int tid = threadIdx.x;
    const int h   = blockIdx.z;
    const int g0  = blockIdx.y * 128;
    const int t0  = blockIdx.x * 128;

    #pragma unroll
    for (int i = 0; i < 16; i++) {
        int idx = i * 256 + tid;
        int m   = idx >> 5;
        int d4  = idx & 31;
        ((float4*)(sA + m * WS_PAD))[d4] =
            ((const float4*)(x + (size_t)(t0 + m) * D_IN))[d4];
        ((float4*)(sB + m * WS_PAD))[d4] =
            ((const float4*)(Wih + ((size_t)h * G3 + g0 + m) * D_IN))[d4];
    }
    __syncthreads();

    const int lane  = tid & 31, warp = tid >> 5;
    const int mi    = lane & 7, gi   = lane >> 3;
    const int warpM = warp >> 2, warpG = warp & 3;
    const int mBase = warpM * 64 + mi * 8;
    const int gBase = warpG * 32 + gi * 8;

    unsigned long long acc[8][8];
    #pragma unroll
    for (int r = 0; r < 8; r++)
        #pragma unroll
        for (int c = 0; c < 8; c++) acc[r][c] = 0ull;

    #pragma unroll
    for (int k4 = 0; k4 < 32; k4++) {
        ulonglong2 av[8], bv[8];
        #pragma unroll
        for (int r = 0; r < 8; r++)
            av[r] = ((const ulonglong2*)(sA + (mBase + r) * WS_PAD))[k4];
        #pragma unroll
        for (int c = 0; c < 8; c++)
            bv[c] = ((const ulonglong2*)(sB + (gBase + c) * WS_PAD))[k4];
        #pragma unroll
        for (int r = 0; r < 8; r++)
            #pragma unroll
            for (int c = 0; c < 8; c++) {
                ffma2(acc[r][c], av[r].x, bv[c].x);
                ffma2(acc[r][c], av[r].y, bv[c].y);
            }
    }

    float bb[8];
    #pragma unroll
    for (int c = 0; c < 8; c++)
        bb[c] = bias[(size_t)h * G3 + g0 + gBase + c];

    #pragma unroll
    for (int r = 0; r < 8; r++) {
        size_t row  = (size_t)t0 + mBase + r;
        float* orow = g_ig + ((size_t)h * T_TOTAL + row) * G3 + g0 + gBase;
        #pragma unroll
        for (int c = 0; c < 8; c++)
            orow[c] = hsum2(acc[r][c]) + bb[c];
    }
}

// ============================================================================
// Kernel 2: one CTA (256 threads) per chain; weights register-resident.
// Thread t: neuron j = t>>1, k-half ks = t&1. Holds 3x64 weights in regs
// (96 f32x2 pairs). Half-dots reduced over the 2-lane group via one shfl_xor.
// Lane ks==0 writes h' to ping-ponged padded SMEM buffer; 1 barrier/step.
// Block b -> head floor(log2(b+1)) so head 0 (longest) runs in wave 1.
// ============================================================================
__global__ void __launch_bounds__(256, 1)
rnn_kernel(const float* __restrict__ Whh,
           const float* __restrict__ bn,
           float* __restrict__ out) {
    __shared__ __align__(16) float hbuf[2][HBUF_LEN];

    const int tid   = threadIdx.x;
    const int j     = tid >> 1;
    const int ks    = tid & 1;
    const int b     = blockIdx.x;
    const int head  = 31 - __clz(b + 1);
    const int chunk = b + 1 - (1 << head);
    const int Tc    = T_TOTAL >> head;

    // Load this thread's 192 weights (rows j, 128+j, 256+j; cols 64ks..64ks+63)
    // into registers as f32x2 pairs. Order in w[g]: [0]=r, [1]=z, [2]=n.
    unsigned long long w[3][32];
    const float* wbase = Whh + (size_t)head * G3 * H_DIM;
    #pragma unroll
    for (int g = 0; g < 3; g++) {
        const float4* src =
            (const float4*)(wbase + (size_t)(g * 128 + j) * H_DIM + ks * 64);
        #pragma unroll
        for (int q = 0; q < 16; q++) {
            float4 v = src[q];
            w[g][2 * q]     = pack2(v.x, v.y);
            w[g][2 * q + 1] = pack2(v.z, v.w);
        }
    }

    if (tid < HBUF_LEN) hbuf[0][tid] = 0.f;
    const float bnj = bn[head * H_DIM + j];
    // Fold bn into the n-dot: only the ks==0 lane seeds its accumulator.
    const unsigned long long an_init = (ks == 0) ? pack2(bnj, 0.f) : 0ull;

    const float* igp  = g_ig + ((size_t)head * T_TOTAL + (size_t)chunk * Tc) * G3;
    float*       outp = out + (size_t)chunk * Tc * OUT_COLS + head * H_DIM + j;

    float igr = __ldcs(igp + j);
    float igz = __ldcs(igp + 128 + j);
    float ign = __ldcs(igp + 256 + j);
    float hprev = 0.f;
    int buf = 0;

    const int hoff = 68 * ks;                 // float offset of this half-slice
    const int hpos = j + 4 * (j >> 6);        // padded write position for h[j]

    __syncthreads();

    #pragma unroll 1
    for (int t = 0; t < Tc; t++) {
        // Prefetch next step's input gates (array slack covers the last step).
        const float* ignext = igp + G3;
        float pr = __ldcs(ignext + j);
        float pz = __ldcs(ignext + 128 + j);
        float pn = __ldcs(ignext + 256 + j);

        // Half dot products; h slice via conflict-free broadcast LDS.128.
        unsigned long long ar0 = 0, ar1 = 0;
        unsigned long long az0 = 0, az1 = 0;
        unsigned long long an0 = an_init, an1 = 0;
        const ulonglong2* hsl = (const ulonglong2*)(hbuf[buf] + hoff);
        #pragma unroll
        for (int c = 0; c < 16; c++) {
            ulonglong2 hv = hsl[c];
            ffma2(an0, w[2][2 * c],     hv.x);
            ffma2(an1, w[2][2 * c + 1], hv.y);
            ffma2(ar0, w[0][2 * c],     hv.x);
            ffma2(ar1, w[0][2 * c + 1], hv.y);
            ffma2(az0, w[1][2 * c],     hv.x);
            ffma2(az1, w[1][2 * c + 1], hv.y);
        }

        // Reduce n first (needed with r), then r (starts MUFU early), then z.
        float dn = hsum2(an0) + hsum2(an1);
        dn += __shfl_xor_sync(0xffffffffu, dn, 1);

        float dr = hsum2(ar0) + hsum2(ar1);
        dr += __shfl_xor_sync(0xffffffffu, dr, 1);
        float r  = fast_sigmoid(igr + dr);

        float dz = hsum2(az0) + hsum2(az1);
        dz += __shfl_xor_sync(0xffffffffu, dz, 1);

        float n  = fast_tanh(ign + r * dn);   // bn already folded into dn
        float z  = fast_sigmoid(igz + dz);
        float hnew = n + z * (hprev - n);

        if (ks == 0) {
            hbuf[buf ^ 1][hpos] = hnew;
            __stcs(outp, hnew);
        }

        hprev = hnew;
        igr = pr; igz = pz; ign = pn;
        igp += G3;
        outp += OUT_COLS;
        __syncthreads();
        buf ^= 1;
    }
}

// ============================================================================
// Launch: GEMM (ig precompute) then recurrence; same stream => ordered.
// ============================================================================
extern "C" void kernel_launch(void* const* d_in, const int* in_sizes, int n_in,
                              void* d_out, int out_size) {
    const float* x   = (const float*)d_in[0];
    const float* Wih = (const float*)d_in[1];
    const float* Whh = (const float*)d_in[2];
    const float* bb  = (const float*)d_in[3];
    const float* bn  = (const float*)d_in[4];
    float* out = (float*)d_out;

    cudaFuncSetAttribute(gemm_ig_kernel,
                         cudaFuncAttributeMaxDynamicSharedMemorySize, GEMM_SMEM);

    gemm_ig_kernel<<<dim3(512, 3, 8), 256, GEMM_SMEM>>>(x, Wih, bb);
    rnn_kernel<<<255, 256>>>(Whh, bn, out);
}

// round 6
// speedup vs baseline: 2.1632x; 1.0865x over previous
#include <cuda_runtime.h>
#include <math.h>

#define T_TOTAL   65536
#define D_IN      128
#define H_DIM     128
#define NUM_HEADS 8
#define G3        384          // 3*H
#define WS_PAD    132          // padded row stride (floats) for GEMM tiles
#define OUT_COLS  (NUM_HEADS * H_DIM)

// Scratch for precomputed input gates ig[h][t][384] (+ slack for prefetch)
__device__ float g_ig[(size_t)NUM_HEADS * T_TOTAL * G3 + G3];

__device__ __forceinline__ void ffma2(unsigned long long& acc,
                                      unsigned long long a,
                                      unsigned long long b) {
    asm("fma.rn.f32x2 %0, %1, %2, %0;" : "+l"(acc) : "l"(a), "l"(b));
}

__device__ __forceinline__ unsigned long long pack2(float lo, float hi) {
    unsigned long long r;
    asm("mov.b64 %0, {%1, %2};" : "=l"(r) : "f"(lo), "f"(hi));
    return r;
}

__device__ __forceinline__ float hsum2(unsigned long long v) {
    float lo, hi;
    asm("mov.b64 {%0, %1}, %2;" : "=f"(lo), "=f"(hi) : "l"(v));
    return lo + hi;
}

__device__ __forceinline__ float fast_sigmoid(float x) {
    float e = __expf(-x);            // validated unclamped in round 4
    return __fdividef(1.f, 1.f + e);
}

__device__ __forceinline__ float fast_tanh(float x) {
    x = fminf(fmaxf(x, -15.f), 15.f);
    float e = __expf(-2.f * x);
    return __fdividef(1.f - e, 1.f + e);
}

// ============================================================================
// Kernel 1: ig[h][t][g] = sum_d x[t,d] * Wih[h,g,d] + b[h,g]
// (validated in rounds 4/5 — unchanged)
// ============================================================================
#define GEMM_SMEM (2 * 128 * WS_PAD * 4)

__global__ void __launch_bounds__(256, 1)
gemm_ig_kernel(const float* __restrict__ x,
               const float* __restrict__ Wih,
               const float* __restrict__ bias) {
    extern __shared__ float sm[];
    float* sA = sm;                  // [128][132]
    float* sB = sm + 128 * WS_PAD;   // [128][132]

    const int tid = threadIdx.x;
    const int h   = blockIdx.z;
    const int g0  = blockIdx.y * 128;
    const int t0  = blockIdx.x * 128;

    #pragma unroll
    for (int i = 0; i < 16; i++) {
        int idx = i * 256 + tid;
        int m   = idx >> 5;
        int d4  = idx & 31;
        ((float4*)(sA + m * WS_PAD))[d4] =
            ((const float4*)(x + (size_t)(t0 + m) * D_IN))[d4];
        ((float4*)(sB + m * WS_PAD))[d4] =
            ((const float4*)(Wih + ((size_t)h * G3 + g0 + m) * D_IN))[d4];
    }
    __syncthreads();

    const int lane  = tid & 31, warp = tid >> 5;
    const int mi    = lane & 7, gi   = lane >> 3;
    const int warpM = warp >> 2, warpG = warp & 3;
    const int mBase = warpM * 64 + mi * 8;
    const int gBase = warpG * 32 + gi * 8;

    unsigned long long acc[8][8];
    #pragma unroll
    for (int r = 0; r < 8; r++)
        #pragma unroll
        for (int c = 0; c < 8; c++) acc[r][c] = 0ull;

    #pragma unroll
    for (int k4 = 0; k4 < 32; k4++) {
        ulonglong2 av[8], bv[8];
        #pragma unroll
        for (int r = 0; r < 8; r++)
            av[r] = ((const ulonglong2*)(sA + (mBase + r) * WS_PAD))[k4];
        #pragma unroll
        for (int c = 0; c < 8; c++)
            bv[c] = ((const ulonglong2*)(sB + (gBase + c) * WS_PAD))[k4];
        #pragma unroll
        for (int r = 0; r < 8; r++)
            #pragma unroll
            for (int c = 0; c < 8; c++) {
                ffma2(acc[r][c], av[r].x, bv[c].x);
                ffma2(acc[r][c], av[r].y, bv[c].y);
            }
    }

    float bb[8];
    #pragma unroll
    for (int c = 0; c < 8; c++)
        bb[c] = bias[(size_t)h * G3 + g0 + gBase + c];

    #pragma unroll
    for (int r = 0; r < 8; r++) {
        size_t row  = (size_t)t0 + mBase + r;
        float* orow = g_ig + ((size_t)h * T_TOTAL + row) * G3 + g0 + gBase;
        #pragma unroll
        for (int c = 0; c < 8; c++)
            orow[c] = hsum2(acc[r][c]) + bb[c];
    }
}

// ============================================================================
// Kernel 2: one CTA (384 threads) per chain. Thread = one full gate row.
//   role = tid>>7:  0 = n-row (warps 0-3),  1 = r-row (4-7),  2 = z-row (8-11)
//   Weight row (128 floats) register-resident as 64 f32x2. Complete dot per
//   thread: no shuffles, no redundant transcendentals. h consumed in 16-float
//   chunks (load-and-use; no full staging => no spills).
//   r,z publish sigmoids to SMEM before bar1; n threads finish the update
//   between bar1 and bar2. bn folded into the n accumulator init.
// Block b -> head floor(log2(b+1)) so head 0 (longest) runs in wave 1.
// ============================================================================
__global__ void __launch_bounds__(384, 1)
rnn_kernel(const float* __restrict__ Whh,
           const float* __restrict__ bn,
           float* __restrict__ out) {
    __shared__ __align__(16) float sh_h[128];
    __shared__ float sh_r[128];
    __shared__ float sh_z[128];

    const int tid   = threadIdx.x;
    const int role  = tid >> 7;          // 0=n, 1=r, 2=z
    const int j     = tid & 127;
    const int b     = blockIdx.x;
    const int head  = 31 - __clz(b + 1);
    const int chunk = b + 1 - (1 << head);
    const int Tc    = T_TOTAL >> head;

    // Weight row index == ig gate offset: n->256+j, r->j, z->128+j.
    const int wrow = (role == 0) ? 256 + j : (role == 1) ? j : 128 + j;

    // Load this thread's full weight row into 64 f32x2 registers.
    unsigned long long w[64];
    {
        const float4* src = (const float4*)
            (Whh + ((size_t)head * G3 + wrow) * H_DIM);
        #pragma unroll
        for (int q = 0; q < 32; q++) {
            float4 v = src[q];
            w[2 * q]     = pack2(v.x, v.y);
            w[2 * q + 1] = pack2(v.z, v.w);
        }
    }

    // Fold bn into the n-dot accumulator init.
    const float bnj = (role == 0) ? bn[head * H_DIM + j] : 0.f;
    const unsigned long long a_init = pack2(bnj, 0.f);

    const float* igp  = g_ig + ((size_t)head * T_TOTAL + (size_t)chunk * Tc) * G3;
    const float* ptr  = igp + wrow;
    float*       outp = out + (size_t)chunk * Tc * OUT_COLS + head * H_DIM + j;

    float ig    = __ldcs(ptr);
    float hprev = 0.f;
    if (role == 1) sh_h[j] = 0.f;
    __syncthreads();

    #pragma unroll 1
    for (int t = 0; t < Tc; t++) {
        // Prefetch next step's input gate (array slack covers the last step).
        float p = __ldcs(ptr + G3);

        // Full 128-dot: 8 chunks of (4 LDS.128 -> 8 ffma2), 4 acc chains.
        unsigned long long a0 = a_init, a1 = 0, a2 = 0, a3 = 0;
        const ulonglong2* hb2 = (const ulonglong2*)sh_h;
        #pragma unroll
        for (int q = 0; q < 8; q++) {
            ulonglong2 v0 = hb2[4 * q + 0];
            ulonglong2 v1 = hb2[4 * q + 1];
            ulonglong2 v2 = hb2[4 * q + 2];
            ulonglong2 v3 = hb2[4 * q + 3];
            ffma2(a0, w[8 * q + 0], v0.x);
            ffma2(a1, w[8 * q + 1], v0.y);
            ffma2(a2, w[8 * q + 2], v1.x);
            ffma2(a3, w[8 * q + 3], v1.y);
            ffma2(a0, w[8 * q + 4], v2.x);
            ffma2(a1, w[8 * q + 5], v2.y);
            ffma2(a2, w[8 * q + 6], v3.x);
            ffma2(a3, w[8 * q + 7], v3.y);
        }
        float d = (hsum2(a0) + hsum2(a1)) + (hsum2(a2) + hsum2(a3));

        if (role != 0) {
            float g = fast_sigmoid(ig + d);
            if (role == 1) sh_r[j] = g;
            else           sh_z[j] = g;
        }

        __syncthreads();   // bar1: r,z published; all h(t) reads complete

        if (role == 0) {
            float rv = sh_r[j];
            float zv = sh_z[j];
            float n  = fast_tanh(ig + rv * d);     // bn already inside d
            float hnew = n + zv * (hprev - n);
            sh_h[j] = hnew;
            __stcs(outp, hnew);
            hprev = hnew;
        }

        __syncthreads();   // bar2: h(t+1) published

        ig = p;
        ptr += G3;
        outp += OUT_COLS;
    }
}

// ============================================================================
// Launch: GEMM (ig precompute) then recurrence; same stream => ordered.
// ============================================================================
extern "C" void kernel_launch(void* const* d_in, const int* in_sizes, int n_in,
                              void* d_out, int out_size) {
    const float* x   = (const float*)d_in[0];
    const float* Wih = (const float*)d_in[1];
    const float* Whh = (const float*)d_in[2];
    const float* bb  = (const float*)d_in[3];
    const float* bn  = (const float*)d_in[4];
    float* out = (float*)d_out;

    cudaFuncSetAttribute(gemm_ig_kernel,
                         cudaFuncAttributeMaxDynamicSharedMemorySize, GEMM_SMEM);

    gemm_ig_kernel<<<dim3(512, 3, 8), 256, GEMM_SMEM>>>(x, Wih, bb);
    rnn_kernel<<<255, 384>>>(Whh, bn, out);
}

// round 7
// speedup vs baseline: 2.2365x; 1.0339x over previous
#include <cuda_runtime.h>
#include <math.h>

#define T_TOTAL   65536
#define D_IN      128
#define H_DIM     128
#define NUM_HEADS 8
#define G3        384          // 3*H
#define OUT_COLS  (NUM_HEADS * H_DIM)

// Scratch for precomputed input gates ig[h][t][384] (+ slack for prefetch)
__device__ float g_ig[(size_t)NUM_HEADS * T_TOTAL * G3 + G3];

__device__ __forceinline__ void ffma2(unsigned long long& acc,
                                      unsigned long long a,
                                      unsigned long long b) {
    asm("fma.rn.f32x2 %0, %1, %2, %0;" : "+l"(acc) : "l"(a), "l"(b));
}

__device__ __forceinline__ unsigned long long pack2(float lo, float hi) {
    unsigned long long r;
    asm("mov.b64 %0, {%1, %2};" : "=l"(r) : "f"(lo), "f"(hi));
    return r;
}

__device__ __forceinline__ float hsum2(unsigned long long v) {
    float lo, hi;
    asm("mov.b64 {%0, %1}, %2;" : "=f"(lo), "=f"(hi) : "l"(v));
    return lo + hi;
}

__device__ __forceinline__ float fast_sigmoid(float x) {
    float e = __expf(-x);            // +-inf handled correctly
    return __fdividef(1.f, 1.f + e);
}

// Clamp-free tanh: 1 - 2/(1 + e^{2x}).  x->+inf: e=inf -> 1; x->-inf: e=0 -> -1.
__device__ __forceinline__ float fast_tanh(float x) {
    float e = __expf(2.f * x);
    return fmaf(-2.f, __fdividef(1.f, 1.f + e), 1.f);
}

// ============================================================================
// Kernel 1: ig[h][t][g] = sum_d x[t,d] * Wih[h,g,d] + b[h,g]
// 128x128x128 tiles, 256 threads, 8x8 micro-tile, f32x2 FMAs.
// XOR swizzle (col ^ ((row>>3)&7)) on BOTH tiles: compute loads are
// conflict-free (8 distinct bank-groups across mi for A, 4 across gi for B).
// ============================================================================
#define WS_F4   33                          // float4 row stride
#define GEMM_SMEM (2 * 128 * WS_F4 * 16)

__global__ void __launch_bounds__(256, 1)
gemm_ig_kernel(const float* __restrict__ x,
               const float* __restrict__ Wih,
               const float* __restrict__ bias) {
    extern __shared__ float sm[];
    float4* sA4 = (float4*)sm;                    // [128][33] float4
    float4* sB4 = sA4 + 128 * WS_F4;              // [128][33] float4

    const int tid = threadIdx.x;
    const int h   = blockIdx.z;
    const int g0  = blockIdx.y * 128;
    const int t0  = blockIdx.x * 128;

    const float4* xg = (const float4*)(x + (size_t)t0 * D_IN);
    const float4* wg = (const float4*)(Wih + ((size_t)h * G3 + g0) * D_IN);

    #pragma unroll
    for (int i = 0; i < 16; i++) {
        int idx = i * 256 + tid;
        int m   = idx >> 5;           // row 0..127
        int d4  = idx & 31;           // float4 col 0..31
        int sw  = (m >> 3) & 7;
        sA4[m * WS_F4 + (d4 ^ sw)] = xg[m * 32 + d4];
        sB4[m * WS_F4 + (d4 ^ sw)] = wg[m * 32 + d4];
    }
    __syncthreads();

    const int lane  = tid & 31, warp = tid >> 5;
    const int mi    = lane & 7, gi   = lane >> 3;
    const int warpM = warp >> 2, warpG = warp & 3;
    const int mBase = warpM * 64 + mi * 8;
    const int gBase = warpG * 32 + gi * 8;
    const int swA   = mi;                       // ((mBase+r)>>3)&7
    const int swB   = (warpG * 4 + gi) & 7;     // ((gBase+c)>>3)&7

    unsigned long long acc[8][8];
    #pragma unroll
    for (int r = 0; r < 8; r++)
        #pragma unroll
        for (int c = 0; c < 8; c++) acc[r][c] = 0ull;

    const ulonglong2* A2 = (const ulonglong2*)sA4;
    const ulonglong2* B2 = (const ulonglong2*)sB4;

    #pragma unroll
    for (int k4 = 0; k4 < 32; k4++) {
        ulonglong2 av[8], bv[8];
        #pragma unroll
        for (int r = 0; r < 8; r++)
            av[r] = A2[(mBase + r) * WS_F4 + (k4 ^ swA)];
        #pragma unroll
        for (int c = 0; c < 8; c++)
            bv[c] = B2[(gBase + c) * WS_F4 + (k4 ^ swB)];
        #pragma unroll
        for (int r = 0; r < 8; r++)
            #pragma unroll
            for (int c = 0; c < 8; c++) {
                ffma2(acc[r][c], av[r].x, bv[c].x);
                ffma2(acc[r][c], av[r].y, bv[c].y);
            }
    }

    float bb[8];
    #pragma unroll
    for (int c = 0; c < 8; c++)
        bb[c] = bias[(size_t)h * G3 + g0 + gBase + c];

    #pragma unroll
    for (int r = 0; r < 8; r++) {
        size_t row  = (size_t)t0 + mBase + r;
        float* orow = g_ig + ((size_t)h * T_TOTAL + row) * G3 + g0 + gBase;
        #pragma unroll
        for (int c = 0; c < 8; c++)
            orow[c] = hsum2(acc[r][c]) + bb[c];
    }
}

// ============================================================================
// Kernel 2: one CTA (384 threads) per chain. Thread = one full gate row.
//   role = tid>>7:  0 = n-row (warps 0-3),  1 = r-row (4-7),  2 = z-row (8-11)
//   Weight row register-resident as 64 f32x2; full dot per thread.
//   bar1 = producer/consumer named barrier (r/z arrive, n sync);
//   bar2 = __syncthreads (h publication). ig folded into r/z acc init.
// Block b -> head floor(log2(b+1)) so head 0 (longest) runs in wave 1.
// ============================================================================
__global__ void __launch_bounds__(384, 1)
rnn_kernel(const float* __restrict__ Whh,
           const float* __restrict__ bn,
           float* __restrict__ out) {
    __shared__ __align__(16) float sh_h[128];
    __shared__ float sh_r[128];
    __shared__ float sh_z[128];

    const int tid   = threadIdx.x;
    const int role  = tid >> 7;          // 0=n, 1=r, 2=z
    const int j     = tid & 127;
    const int b     = blockIdx.x;
    const int head  = 31 - __clz(b + 1);
    const int chunk = b + 1 - (1 << head);
    const int Tc    = T_TOTAL >> head;

    // Weight row index == ig gate offset: n->256+j, r->j, z->128+j.
    const int wrow = (role == 0) ? 256 + j : (role == 1) ? j : 128 + j;

    unsigned long long w[64];
    {
        const float4* src = (const float4*)
            (Whh + ((size_t)head * G3 + wrow) * H_DIM);
        #pragma unroll
        for (int q = 0; q < 32; q++) {
            float4 v = src[q];
            w[2 * q]     = pack2(v.x, v.y);
            w[2 * q + 1] = pack2(v.z, v.w);
        }
    }

    const float bnj = (role == 0) ? bn[head * H_DIM + j] : 0.f;

    const float* igp  = g_ig + ((size_t)head * T_TOTAL + (size_t)chunk * Tc) * G3;
    const float* ptr  = igp + wrow;
    float*       outp = out + (size_t)chunk * Tc * OUT_COLS + head * H_DIM + j;

    float ig    = __ldcs(ptr);
    float hprev = 0.f;
    if (role == 1) sh_h[j] = 0.f;
    __syncthreads();

    #pragma unroll 1
    for (int t = 0; t < Tc; t++) {
        // Prefetch next step's input gate (array slack covers the last step).
        float p = __ldcs(ptr + G3);

        // Accumulator init: n folds bn; r/z fold their ig (saves a tail FADD).
        unsigned long long a0 =
            (role == 0) ? pack2(bnj, 0.f) : pack2(ig, 0.f);
        unsigned long long a1 = 0, a2 = 0, a3 = 0;

        // Full 128-dot: 8 chunks of (4 LDS.128 -> 8 ffma2), 4 acc chains.
        const ulonglong2* hb2 = (const ulonglong2*)sh_h;
        #pragma unroll
        for (int q = 0; q < 8; q++) {
            ulonglong2 v0 = hb2[4 * q + 0];
            ulonglong2 v1 = hb2[4 * q + 1];
            ulonglong2 v2 = hb2[4 * q + 2];
            ulonglong2 v3 = hb2[4 * q + 3];
            ffma2(a0, w[8 * q + 0], v0.x);
            ffma2(a1, w[8 * q + 1], v0.y);
            ffma2(a2, w[8 * q + 2], v1.x);
            ffma2(a3, w[8 * q + 3], v1.y);
            ffma2(a0, w[8 * q + 4], v2.x);
            ffma2(a1, w[8 * q + 5], v2.y);
            ffma2(a2, w[8 * q + 6], v3.x);
            ffma2(a3, w[8 * q + 7], v3.y);
        }
        float d = (hsum2(a0) + hsum2(a1)) + (hsum2(a2) + hsum2(a3));

        if (role != 0) {
            float g = fast_sigmoid(d);          // ig already folded in
            if (role == 1) sh_r[j] = g;
            else           sh_z[j] = g;
            // Producer arrive: non-blocking; memory ordering provided by the
            // consumer's bar.sync on the same barrier.
            asm volatile("bar.arrive 1, 384;" ::: "memory");
        } else {
            asm volatile("bar.sync 1, 384;" ::: "memory");  // wait r,z
            float rv = sh_r[j];
            float zv = sh_z[j];
            float n  = fast_tanh(ig + rv * d);  // bn already inside d
            float hnew = n + zv * (hprev - n);
            sh_h[j] = hnew;
            __stcs(outp, hnew);
            hprev = hnew;
        }

        __syncthreads();   // bar2: h(t+1) published

        ig = p;
        ptr += G3;
        outp += OUT_COLS;
    }
}

// ============================================================================
// Launch: GEMM (ig precompute) then recurrence; same stream => ordered.
// ============================================================================
extern "C" void kernel_launch(void* const* d_in, const int* in_sizes, int n_in,
                              void* d_out, int out_size) {
    const float* x   = (const float*)d_in[0];
    const float* Wih = (const float*)d_in[1];
    const float* Whh = (const float*)d_in[2];
    const float* bb  = (const float*)d_in[3];
    const float* bn  = (const float*)d_in[4];
    float* out = (float*)d_out;

    cudaFuncSetAttribute(gemm_ig_kernel,
                         cudaFuncAttributeMaxDynamicSharedMemorySize, GEMM_SMEM);

    gemm_ig_kernel<<<dim3(512, 3, 8), 256, GEMM_SMEM>>>(x, Wih, bb);
    rnn_kernel<<<255, 384>>>(Whh, bn, out);
}